// round 12
// baseline (speedup 1.0000x reference)
#include <cuda_runtime.h>
#include <cuda_bf16.h>
#include <math.h>
#include <stdint.h>

#define H_   16
#define KV_  4
#define D_   128
#define B_   2
#define L_   2048
#define HID  2048
#define M_   (B_*L_)
#define WIN_ 512
#define NQKV 3072
#define KK   2048

// ---------------- scratch ----------------
__device__ __align__(16) __nv_bfloat16 g_xh   [(size_t)M_  * KK];
__device__ __align__(16) __nv_bfloat16 g_xl   [(size_t)M_  * KK];
__device__ __align__(16) __nv_bfloat16 g_wqkvh[(size_t)NQKV * KK];
__device__ __align__(16) __nv_bfloat16 g_wqkvl[(size_t)NQKV * KK];
__device__ __align__(16) __nv_bfloat16 g_woh  [(size_t)HID * KK];
__device__ __align__(16) __nv_bfloat16 g_wol  [(size_t)HID * KK];
__device__ __align__(16) __nv_bfloat16 g_aoh  [(size_t)M_  * KK];
__device__ __align__(16) __nv_bfloat16 g_aol  [(size_t)M_  * KK];
__device__ __align__(16) float g_qkvbuf[(size_t)M_ * NQKV];
__device__ __align__(16) __nv_bfloat16 g_qh [(size_t)B_*H_*L_*D_];
__device__ __align__(16) __nv_bfloat16 g_ql [(size_t)B_*H_*L_*D_];
__device__ __align__(16) __nv_bfloat16 g_kh [(size_t)B_*KV_*L_*D_];
__device__ __align__(16) __nv_bfloat16 g_kl [(size_t)B_*KV_*L_*D_];
__device__ __align__(16) __nv_bfloat16 g_vth[(size_t)B_*KV_*D_*L_];
__device__ __align__(16) __nv_bfloat16 g_vtl[(size_t)B_*KV_*D_*L_];

#define CP_ASYNC16(dst, src) \
    asm volatile("cp.async.cg.shared.global [%0], [%1], 16;" :: "r"(dst), "l"(src))
#define CP_COMMIT() asm volatile("cp.async.commit_group;")
#define CP_WAIT(n)  asm volatile("cp.async.wait_group %0;" :: "n"(n))

#define LDSM_X4(r0,r1,r2,r3,addr) \
    asm volatile("ldmatrix.sync.aligned.m8n8.x4.shared.b16 {%0,%1,%2,%3}, [%4];" \
        : "=r"(r0),"=r"(r1),"=r"(r2),"=r"(r3) : "r"(addr))
#define MMA16816(c,a0,a1,a2,a3,b0,b1) \
    asm volatile("mma.sync.aligned.m16n8k16.row.col.f32.bf16.bf16.f32 " \
        "{%0,%1,%2,%3},{%4,%5,%6,%7},{%8,%9},{%0,%1,%2,%3};" \
        : "+f"((c)[0]),"+f"((c)[1]),"+f"((c)[2]),"+f"((c)[3]) \
        : "r"(a0),"r"(a1),"r"(a2),"r"(a3),"r"(b0),"r"(b1))

// ---------------- fp32 -> hi/lo bf16 planes ----------------
__global__ __launch_bounds__(256) void convert_hl(
    const float* __restrict__ src,
    __nv_bfloat16* __restrict__ dh, __nv_bfloat16* __restrict__ dl, int total)
{
    int i = (blockIdx.x * 256 + threadIdx.x) * 4;
    if (i >= total) return;
    float4 v = *(const float4*)(src + i);
    float f[4] = {v.x, v.y, v.z, v.w};
    __nv_bfloat16 hi[4], lo[4];
#pragma unroll
    for (int e = 0; e < 4; e++) {
        hi[e] = __float2bfloat16_rn(f[e]);
        lo[e] = __float2bfloat16_rn(f[e] - __bfloat162float(hi[e]));
    }
    __nv_bfloat162 hp0 = {hi[0], hi[1]}, hp1 = {hi[2], hi[3]};
    __nv_bfloat162 lp0 = {lo[0], lo[1]}, lp1 = {lo[2], lo[3]};
    ((__nv_bfloat162*)(dh + i))[0] = hp0; ((__nv_bfloat162*)(dh + i))[1] = hp1;
    ((__nv_bfloat162*)(dl + i))[0] = lp0; ((__nv_bfloat162*)(dl + i))[1] = lp1;
}

// ---------------- 3-pass split-bf16 GEMM, CTA tile 128x256 ----------------
// 256 threads (8 warps as 2m x 4n, warp tile 64x64), BK=32, 3-stage cp.async.
// C[m,n] = sum_k ah*bh + al*bh + ah*bl
#define A_B 10240                     // Ah tile bytes (128 rows x 80B)
#define B_B 20480                     // Bh tile bytes (256 rows x 80B)
#define ST3 (2 * A_B + 2 * B_B)       // 61440 per stage: Ah|Al|Bh|Bl
#define GSM3 (3 * ST3)                // 184320

__global__ __launch_bounds__(256, 1) void gemm_hl(
    const __nv_bfloat16* __restrict__ Ah, const __nv_bfloat16* __restrict__ Al,
    const __nv_bfloat16* __restrict__ Bh, const __nv_bfloat16* __restrict__ Bl,
    float* __restrict__ C, int M, int N, int K)
{
    extern __shared__ __nv_bfloat16 gsm[];
    const uint32_t smb = (uint32_t)__cvta_generic_to_shared(gsm);

    const int tid  = threadIdx.x;
    const int m0   = blockIdx.y * 128;
    const int n0   = blockIdx.x * 256;
    const int wid  = tid >> 5;
    const int lane = tid & 31;
    const int wm   = wid & 1;          // 2 m-halves of 64
    const int wn   = wid >> 1;         // 4 n-quarters of 64

    float acc[4][8][4];
#pragma unroll
    for (int i = 0; i < 4; i++)
#pragma unroll
        for (int j = 0; j < 8; j++)
#pragma unroll
            for (int r = 0; r < 4; r++) acc[i][j][r] = 0.f;

    auto load_stage = [&](int st, int kt) {
        const int k0 = kt * 32;
        const uint32_t base = smb + st * ST3;
        // A planes: 512 chunks each (128 rows x 4x16B payload)
#pragma unroll
        for (int it = 0; it < 2; it++) {
            int t = tid + it * 256;
            int r = t >> 2, c = t & 3;
            uint32_t so = (uint32_t)(r * 80 + c * 16);
            size_t go = (size_t)(m0 + r) * K + k0 + c * 8;
            CP_ASYNC16(base + so,       Ah + go);
            CP_ASYNC16(base + A_B + so, Al + go);
        }
        // B planes: 1024 chunks each (256 rows x 4x16B payload)
#pragma unroll
        for (int it = 0; it < 4; it++) {
            int t = tid + it * 256;
            int r = t >> 2, c = t & 3;
            uint32_t so = (uint32_t)(r * 80 + c * 16);
            size_t go = (size_t)(n0 + r) * K + k0 + c * 8;
            CP_ASYNC16(base + 2 * A_B + so,       Bh + go);
            CP_ASYNC16(base + 2 * A_B + B_B + so, Bl + go);
        }
    };

    const int KT = K / 32;
    load_stage(0, 0); CP_COMMIT();
    load_stage(1, 1); CP_COMMIT();

    int slot = 0;
    for (int kt = 0; kt < KT; kt++) {
        CP_WAIT(1);
        __syncthreads();
        if (kt + 2 < KT) {
            int s2 = slot + 2; if (s2 >= 3) s2 -= 3;
            load_stage(s2, kt + 2);
        }
        CP_COMMIT();

        const uint32_t sb  = smb + slot * ST3;
        const uint32_t sbl = sb + A_B;
        const uint32_t bbh = sb + 2 * A_B;
        const uint32_t bbl = bbh + B_B;

#pragma unroll
        for (int ks = 0; ks < 2; ks++) {
            uint32_t ah[4][4], al4[4][4];
#pragma unroll
            for (int mi = 0; mi < 4; mi++) {
                int row = wm * 64 + mi * 16 + (lane & 15);
                uint32_t off = row * 80 + ks * 32 + ((lane >> 4) << 4);
                LDSM_X4(ah[mi][0], ah[mi][1], ah[mi][2], ah[mi][3], sb + off);
                LDSM_X4(al4[mi][0], al4[mi][1], al4[mi][2], al4[mi][3], sbl + off);
            }
            uint32_t bh4[4][4], bl4[4][4];
#pragma unroll
            for (int ng = 0; ng < 4; ng++) {
                int row = wn * 64 + ng * 16 + (lane & 15);
                uint32_t off = row * 80 + ks * 32 + ((lane >> 4) << 4);
                LDSM_X4(bh4[ng][0], bh4[ng][1], bh4[ng][2], bh4[ng][3], bbh + off);
                LDSM_X4(bl4[ng][0], bl4[ng][1], bl4[ng][2], bl4[ng][3], bbl + off);
            }
#pragma unroll
            for (int mi = 0; mi < 4; mi++)
#pragma unroll
                for (int ng = 0; ng < 4; ng++) {
                    float* c0 = acc[mi][2 * ng];
                    float* c1 = acc[mi][2 * ng + 1];
                    MMA16816(c0, ah[mi][0], ah[mi][1], ah[mi][2], ah[mi][3],
                             bh4[ng][0], bh4[ng][2]);
                    MMA16816(c0, al4[mi][0], al4[mi][1], al4[mi][2], al4[mi][3],
                             bh4[ng][0], bh4[ng][2]);
                    MMA16816(c0, ah[mi][0], ah[mi][1], ah[mi][2], ah[mi][3],
                             bl4[ng][0], bl4[ng][2]);
                    MMA16816(c1, ah[mi][0], ah[mi][1], ah[mi][2], ah[mi][3],
                             bh4[ng][1], bh4[ng][3]);
                    MMA16816(c1, al4[mi][0], al4[mi][1], al4[mi][2], al4[mi][3],
                             bh4[ng][1], bh4[ng][3]);
                    MMA16816(c1, ah[mi][0], ah[mi][1], ah[mi][2], ah[mi][3],
                             bl4[ng][1], bl4[ng][3]);
                }
        }
        if (++slot == 3) slot = 0;
    }

    const int tr = lane >> 2;
    const int tc = (lane & 3) * 2;
#pragma unroll
    for (int mi = 0; mi < 4; mi++)
#pragma unroll
        for (int ni = 0; ni < 8; ni++) {
            int row = m0 + wm * 64 + mi * 16 + tr;
            int col = n0 + wn * 64 + ni * 8 + tc;
            *(float2*)(C + (size_t)row * N + col) =
                make_float2(acc[mi][ni][0], acc[mi][ni][1]);
            *(float2*)(C + (size_t)(row + 8) * N + col) =
                make_float2(acc[mi][ni][2], acc[mi][ni][3]);
        }
}

// ---------------- QK RMSNorm + RoPE + split outputs (+ V split/transpose) ----------------
__global__ __launch_bounds__(128) void norm_rope_split(
    const float* __restrict__ qkv,
    const float* __restrict__ cosT, const float* __restrict__ sinT,
    const float* __restrict__ qw,   const float* __restrict__ kw,
    __nv_bfloat16* __restrict__ qh, __nv_bfloat16* __restrict__ ql,
    __nv_bfloat16* __restrict__ kh, __nv_bfloat16* __restrict__ kl,
    __nv_bfloat16* __restrict__ vth, __nv_bfloat16* __restrict__ vtl)
{
    const int l  = blockIdx.x;
    const int b  = blockIdx.y;
    const int hh = blockIdx.z;
    const int d  = threadIdx.x;
    const size_t m = (size_t)b * L_ + l;

    if (hh >= H_ + KV_) {
        const int kv = hh - (H_ + KV_);
        float x = qkv[m * NQKV + HID + KV_ * D_ + kv * D_ + d];
        __nv_bfloat16 hi = __float2bfloat16_rn(x);
        __nv_bfloat16 lo = __float2bfloat16_rn(x - __bfloat162float(hi));
        size_t idx = ((size_t)(b * KV_ + kv) * D_ + d) * L_ + l;
        vth[idx] = hi; vtl[idx] = lo;
        return;
    }

    float x;
    if (hh < H_) x = qkv[m * NQKV + hh * D_ + d];
    else         x = qkv[m * NQKV + HID + (hh - H_) * D_ + d];

    __shared__ float red[4];
    __shared__ float xn[128];

    float v = x * x;
#pragma unroll
    for (int o = 16; o > 0; o >>= 1) v += __shfl_xor_sync(0xffffffffu, v, o);
    if ((d & 31) == 0) red[d >> 5] = v;
    __syncthreads();
    float total = red[0] + red[1] + red[2] + red[3];
    float rms = rsqrtf(total * (1.0f / 128.0f) + 1e-6f);
    float w = (hh < H_) ? qw[d] : kw[d];
    float xv = x * rms * w;
    xn[d] = xv;
    __syncthreads();

    float c = cosT[l * D_ + d];
    float s = sinT[l * D_ + d];
    float rot = (d < 64) ? -xn[d + 64] : xn[d - 64];
    float out = xv * c + rot * s;

    __nv_bfloat16 hi = __float2bfloat16_rn(out);
    __nv_bfloat16 lo = __float2bfloat16_rn(out - __bfloat162float(hi));
    if (hh < H_) {
        size_t idx = (((size_t)(b * H_ + hh)) * L_ + l) * D_ + d;
        qh[idx] = hi; ql[idx] = lo;
    } else {
        size_t idx = (((size_t)(b * KV_ + (hh - H_))) * L_ + l) * D_ + d;
        kh[idx] = hi; kl[idx] = lo;
    }
}

// ---------------- tensor-core banded flash attention, double-buffered KV ----------------
#define AQH 0
#define AQL 17408
#define AKV0 34816
#define AKVSTR 35840
#define ATTN_SMEM_ELEMS (AKV0 + 2 * AKVSTR)
#define ATTN_SMEM_BYTES (ATTN_SMEM_ELEMS * 2)

__device__ __forceinline__ uint32_t pkhi(float x, float y) {
    __nv_bfloat162 t = __floats2bfloat162_rn(x, y);
    return *reinterpret_cast<uint32_t*>(&t);
}
__device__ __forceinline__ uint32_t pklo(float x, float y) {
    __nv_bfloat16 hx = __float2bfloat16_rn(x), hy = __float2bfloat16_rn(y);
    __nv_bfloat162 t = __floats2bfloat162_rn(x - __bfloat162float(hx),
                                             y - __bfloat162float(hy));
    return *reinterpret_cast<uint32_t*>(&t);
}

__global__ __launch_bounds__(256) void attn_mma_kernel(
    const __nv_bfloat16* __restrict__ qhg, const __nv_bfloat16* __restrict__ qlg,
    const __nv_bfloat16* __restrict__ khg, const __nv_bfloat16* __restrict__ klg,
    const __nv_bfloat16* __restrict__ vhg, const __nv_bfloat16* __restrict__ vlg,
    __nv_bfloat16* __restrict__ aoh, __nv_bfloat16* __restrict__ aol)
{
    extern __shared__ __nv_bfloat16 sm[];

    const int tid  = threadIdx.x;
    const int wid  = tid >> 5;
    const int lane = tid & 31;
    const int qb   = blockIdx.x;
    const int bh   = blockIdx.y;
    const int b    = bh >> 4;
    const int h    = bh & 15;
    const int kv   = h >> 2;
    const int q0   = qb * 128;
    const float scale = 0.08838834764831845f;

    const uint32_t smb  = (uint32_t)__cvta_generic_to_shared(sm);
    const uint32_t qh_b = smb + AQH * 2;
    const uint32_t ql_b = smb + AQL * 2;

    const __nv_bfloat16* kh_src = khg + ((size_t)(b * KV_ + kv)) * L_ * D_;
    const __nv_bfloat16* kl_src = klg + ((size_t)(b * KV_ + kv)) * L_ * D_;
    const __nv_bfloat16* vh_src = vhg + ((size_t)(b * KV_ + kv) * D_) * L_;
    const __nv_bfloat16* vl_src = vlg + ((size_t)(b * KV_ + kv) * D_) * L_;

    auto load_kv = [&](int st, int tk) {
        const int j0 = tk * 64;
        const uint32_t kvb  = smb + (AKV0 + st * AKVSTR) * 2;
        const uint32_t khb  = kvb;
        const uint32_t klb  = kvb + 8704 * 2;
        const uint32_t vhb  = kvb + 17408 * 2;
        const uint32_t vlb  = kvb + 26624 * 2;
#pragma unroll
        for (int t = tid; t < 64 * 16; t += 256) {
            int r = t >> 4, c = (t & 15) * 8;
            uint32_t so = (r * 136 + c) * 2;
            size_t go = (size_t)(j0 + r) * D_ + c;
            CP_ASYNC16(khb + so, kh_src + go);
            CP_ASYNC16(klb + so, kl_src + go);
        }
#pragma unroll
        for (int t = tid; t < 128 * 8; t += 256) {
            int d = t >> 3, c = (t & 7) * 8;
            uint32_t so = (d * 72 + c) * 2;
            size_t go = (size_t)d * L_ + j0 + c;
            CP_ASYNC16(vhb + so, vh_src + go);
            CP_ASYNC16(vlb + so, vl_src + go);
        }
    };

    {
        const __nv_bfloat16* ph = qhg + (((size_t)(b * H_ + h)) * L_ + q0) * D_;
        const __nv_bfloat16* pl = qlg + (((size_t)(b * H_ + h)) * L_ + q0) * D_;
        for (int t = tid; t < 128 * 16; t += 256) {
            int r = t >> 4, c = (t & 15) * 8;
            *(uint4*)(sm + AQH + r * 136 + c) = *(const uint4*)(ph + r * 128 + c);
            *(uint4*)(sm + AQL + r * 136 + c) = *(const uint4*)(pl + r * 128 + c);
        }
    }

    float o[16][4];
#pragma unroll
    for (int n = 0; n < 16; n++)
#pragma unroll
        for (int e = 0; e < 4; e++) o[n][e] = 0.f;
    float mrow[2] = {-1e30f, -1e30f};
    float lrow[2] = {0.f, 0.f};

    const int i1 = q0 + wid * 16 + (lane >> 2);
    const int i2 = i1 + 8;

    int t_lo = (q0 - WIN_) >> 6; if (t_lo < 0) t_lo = 0;
    int t_hi = (q0 + 127 + WIN_) >> 6; if (t_hi > L_ / 64 - 1) t_hi = L_ / 64 - 1;

    load_kv(0, t_lo);
    CP_COMMIT();

    for (int tk = t_lo; tk <= t_hi; tk++) {
        const int st = (tk - t_lo) & 1;
        const int j0 = tk * 64;

        CP_WAIT(0);
        __syncthreads();
        if (tk < t_hi) { load_kv(st ^ 1, tk + 1); }
        CP_COMMIT();

        const uint32_t kvb  = smb + (AKV0 + st * AKVSTR) * 2;
        const uint32_t kh_b = kvb;
        const uint32_t kl_b = kvb + 8704 * 2;
        const uint32_t vh_b = kvb + 17408 * 2;
        const uint32_t vl_b = kvb + 26624 * 2;

        float s[8][4];
#pragma unroll
        for (int n = 0; n < 8; n++)
#pragma unroll
            for (int e = 0; e < 4; e++) s[n][e] = 0.f;

#pragma unroll
        for (int pass = 0; pass < 3; pass++) {
            const uint32_t ab = (pass == 1) ? ql_b : qh_b;
            const uint32_t bb = (pass == 2) ? kl_b : kh_b;
#pragma unroll
            for (int k8 = 0; k8 < 8; k8++) {
                uint32_t a0, a1, a2, a3;
                uint32_t aaddr = ab + ((wid * 16 + (lane & 15)) * 136
                                       + k8 * 16 + ((lane >> 4) * 8)) * 2;
                LDSM_X4(a0, a1, a2, a3, aaddr);
#pragma unroll
                for (int n2 = 0; n2 < 4; n2++) {
                    uint32_t b0, b1, b2, b3;
                    uint32_t baddr = bb + ((n2 * 16 + (lane & 15)) * 136
                                           + k8 * 16 + ((lane >> 4) * 8)) * 2;
                    LDSM_X4(b0, b1, b2, b3, baddr);
                    MMA16816(s[2 * n2],     a0, a1, a2, a3, b0, b2);
                    MMA16816(s[2 * n2 + 1], a0, a1, a2, a3, b1, b3);
                }
            }
        }

#pragma unroll
        for (int n = 0; n < 8; n++) {
            const int jc = j0 + n * 8 + (lane & 3) * 2;
#pragma unroll
            for (int e = 0; e < 4; e++) {
                const int i = (e < 2) ? i1 : i2;
                const int j = jc + (e & 1);
                const bool valid = (unsigned)(i - j + WIN_) <= (unsigned)(2 * WIN_);
                s[n][e] = valid ? s[n][e] * scale : -1e30f;
            }
        }

        float m1 = -1e30f, m2 = -1e30f;
#pragma unroll
        for (int n = 0; n < 8; n++) {
            m1 = fmaxf(m1, fmaxf(s[n][0], s[n][1]));
            m2 = fmaxf(m2, fmaxf(s[n][2], s[n][3]));
        }
        m1 = fmaxf(m1, __shfl_xor_sync(0xffffffffu, m1, 1));
        m1 = fmaxf(m1, __shfl_xor_sync(0xffffffffu, m1, 2));
        m2 = fmaxf(m2, __shfl_xor_sync(0xffffffffu, m2, 1));
        m2 = fmaxf(m2, __shfl_xor_sync(0xffffffffu, m2, 2));
        const float mn1 = fmaxf(mrow[0], m1);
        const float mn2 = fmaxf(mrow[1], m2);
        const float al1 = __expf(mrow[0] - mn1);
        const float al2 = __expf(mrow[1] - mn2);
        float ls1 = 0.f, ls2 = 0.f;
#pragma unroll
        for (int n = 0; n < 8; n++) {
            s[n][0] = __expf(s[n][0] - mn1);
            s[n][1] = __expf(s[n][1] - mn1);
            s[n][2] = __expf(s[n][2] - mn2);
            s[n][3] = __expf(s[n][3] - mn2);
            ls1 += s[n][0] + s[n][1];
            ls2 += s[n][2] + s[n][3];
        }
        ls1 += __shfl_xor_sync(0xffffffffu, ls1, 1);
        ls1 += __shfl_xor_sync(0xffffffffu, ls1, 2);
        ls2 += __shfl_xor_sync(0xffffffffu, ls2, 1);
        ls2 += __shfl_xor_sync(0xffffffffu, ls2, 2);
        lrow[0] = al1 * lrow[0] + ls1;
        lrow[1] = al2 * lrow[1] + ls2;
        mrow[0] = mn1;
        mrow[1] = mn2;
#pragma unroll
        for (int n = 0; n < 16; n++) {
            o[n][0] *= al1; o[n][1] *= al1;
            o[n][2] *= al2; o[n][3] *= al2;
        }

#pragma unroll
        for (int kk = 0; kk < 4; kk++) {
            const int t0 = 2 * kk, t1 = 2 * kk + 1;
            uint32_t ah[4], al[4];
            ah[0] = pkhi(s[t0][0], s[t0][1]); ah[1] = pkhi(s[t0][2], s[t0][3]);
            ah[2] = pkhi(s[t1][0], s[t1][1]); ah[3] = pkhi(s[t1][2], s[t1][3]);
            al[0] = pklo(s[t0][0], s[t0][1]); al[1] = pklo(s[t0][2], s[t0][3]);
            al[2] = pklo(s[t1][0], s[t1][1]); al[3] = pklo(s[t1][2], s[t1][3]);
#pragma unroll
            for (int n2 = 0; n2 < 8; n2++) {
                uint32_t h0, h1, h2, h3, l0, l1, l2, l3;
                uint32_t va = ((n2 * 16 + (lane & 15)) * 72
                               + kk * 16 + ((lane >> 4) * 8)) * 2;
                LDSM_X4(h0, h1, h2, h3, vh_b + va);
                LDSM_X4(l0, l1, l2, l3, vl_b + va);
                MMA16816(o[2 * n2], ah[0], ah[1], ah[2], ah[3], h0, h2);
                MMA16816(o[2 * n2], al[0], al[1], al[2], al[3], h0, h2);
                MMA16816(o[2 * n2], ah[0], ah[1], ah[2], ah[3], l0, l2);
                MMA16816(o[2 * n2 + 1], ah[0], ah[1], ah[2], ah[3], h1, h3);
                MMA16816(o[2 * n2 + 1], al[0], al[1], al[2], al[3], h1, h3);
                MMA16816(o[2 * n2 + 1], ah[0], ah[1], ah[2], ah[3], l1, l3);
            }
        }
    }

    const float inv1 = 1.0f / lrow[0];
    const float inv2 = 1.0f / lrow[1];
    const size_t m1r = (size_t)b * L_ + i1;
    const size_t m2r = (size_t)b * L_ + i2;
#pragma unroll
    for (int n = 0; n < 16; n++) {
        const int col = h * 128 + n * 8 + (lane & 3) * 2;
        {
            float v0 = o[n][0] * inv1, v1 = o[n][1] * inv1;
            __nv_bfloat16 h0 = __float2bfloat16_rn(v0), h1v = __float2bfloat16_rn(v1);
            __nv_bfloat162 hp = {h0, h1v};
            __nv_bfloat162 lp = {__float2bfloat16_rn(v0 - __bfloat162float(h0)),
                                 __float2bfloat16_rn(v1 - __bfloat162float(h1v))};
            *(__nv_bfloat162*)(aoh + m1r * KK + col) = hp;
            *(__nv_bfloat162*)(aol + m1r * KK + col) = lp;
        }
        {
            float v0 = o[n][2] * inv2, v1 = o[n][3] * inv2;
            __nv_bfloat16 h0 = __float2bfloat16_rn(v0), h1v = __float2bfloat16_rn(v1);
            __nv_bfloat162 hp = {h0, h1v};
            __nv_bfloat162 lp = {__float2bfloat16_rn(v0 - __bfloat162float(h0)),
                                 __float2bfloat16_rn(v1 - __bfloat162float(h1v))};
            *(__nv_bfloat162*)(aoh + m2r * KK + col) = hp;
            *(__nv_bfloat162*)(aol + m2r * KK + col) = lp;
        }
    }
}

// ---------------- launch ----------------
extern "C" void kernel_launch(void* const* d_in, const int* in_sizes, int n_in,
                              void* d_out, int out_size)
{
    const float* x    = (const float*)d_in[0];
    const float* cosT = (const float*)d_in[1];
    const float* sinT = (const float*)d_in[2];
    const float* Wq   = (const float*)d_in[3];
    const float* Wk   = (const float*)d_in[4];
    const float* Wv   = (const float*)d_in[5];
    const float* Wo   = (const float*)d_in[6];
    const float* qw   = (const float*)d_in[7];
    const float* kw   = (const float*)d_in[8];
    float* out = (float*)d_out;

    __nv_bfloat16 *xh, *xl, *wqkvh, *wqkvl, *woh, *wol, *aoh, *aol;
    __nv_bfloat16 *qh, *ql, *kh, *kl, *vth, *vtl;
    float *qkvbuf;
    cudaGetSymbolAddress((void**)&xh,     g_xh);
    cudaGetSymbolAddress((void**)&xl,     g_xl);
    cudaGetSymbolAddress((void**)&wqkvh,  g_wqkvh);
    cudaGetSymbolAddress((void**)&wqkvl,  g_wqkvl);
    cudaGetSymbolAddress((void**)&woh,    g_woh);
    cudaGetSymbolAddress((void**)&wol,    g_wol);
    cudaGetSymbolAddress((void**)&aoh,    g_aoh);
    cudaGetSymbolAddress((void**)&aol,    g_aol);
    cudaGetSymbolAddress((void**)&qkvbuf, g_qkvbuf);
    cudaGetSymbolAddress((void**)&qh,     g_qh);
    cudaGetSymbolAddress((void**)&ql,     g_ql);
    cudaGetSymbolAddress((void**)&kh,     g_kh);
    cudaGetSymbolAddress((void**)&kl,     g_kl);
    cudaGetSymbolAddress((void**)&vth,    g_vth);
    cudaGetSymbolAddress((void**)&vtl,    g_vtl);

    // hi/lo conversions
    {
        int tot = M_ * HID;
        convert_hl<<<tot / 1024, 256>>>(x, xh, xl, tot);
        tot = HID * HID;
        convert_hl<<<tot / 1024, 256>>>(Wq, wqkvh, wqkvl, tot);
        tot = KV_ * D_ * HID;
        convert_hl<<<tot / 1024, 256>>>(Wk, wqkvh + (size_t)HID * KK,
                                        wqkvl + (size_t)HID * KK, tot);
        convert_hl<<<tot / 1024, 256>>>(Wv, wqkvh + (size_t)(HID + KV_ * D_) * KK,
                                        wqkvl + (size_t)(HID + KV_ * D_) * KK, tot);
        tot = HID * HID;
        convert_hl<<<tot / 1024, 256>>>(Wo, woh, wol, tot);
    }

    cudaFuncSetAttribute(gemm_hl,
                         cudaFuncAttributeMaxDynamicSharedMemorySize, GSM3);

    // fused QKV projection (tile 128x256)
    gemm_hl<<<dim3(NQKV / 256, M_ / 128), 256, GSM3>>>(
        xh, xl, wqkvh, wqkvl, qkvbuf, M_, NQKV, KK);

    // RMSNorm + RoPE + split outputs
    norm_rope_split<<<dim3(L_, B_, H_ + 2 * KV_), 128>>>(
        qkvbuf, cosT, sinT, qw, kw, qh, ql, kh, kl, vth, vtl);

    // tensor-core banded flash attention
    cudaFuncSetAttribute(attn_mma_kernel,
                         cudaFuncAttributeMaxDynamicSharedMemorySize, ATTN_SMEM_BYTES);
    attn_mma_kernel<<<dim3(L_ / 128, B_ * H_), 256, ATTN_SMEM_BYTES>>>(
        qh, ql, kh, kl, vth, vtl, aoh, aol);

    // output projection (tile 128x256)
    gemm_hl<<<dim3(HID / 256, M_ / 128), 256, GSM3>>>(
        aoh, aol, woh, wol, out, M_, HID, KK);
}

// round 15
// speedup vs baseline: 1.4170x; 1.4170x over previous
#include <cuda_runtime.h>
#include <cuda_fp16.h>
#include <math.h>
#include <stdint.h>

#define H_   16
#define KV_  4
#define D_   128
#define B_   2
#define L_   2048
#define HID  2048
#define M_   (B_*L_)
#define WIN_ 512
#define NQKV 3072
#define KK   2048

// ---------------- scratch ----------------
__device__ __align__(16) __half g_xh   [(size_t)M_  * KK];
__device__ __align__(16) __half g_xl   [(size_t)M_  * KK];
__device__ __align__(16) __half g_wqkvh[(size_t)NQKV * KK];
__device__ __align__(16) __half g_woh  [(size_t)HID * KK];
__device__ __align__(16) __half g_aoh  [(size_t)M_  * KK];
__device__ __align__(16) __half g_aol  [(size_t)M_  * KK];
__device__ __align__(16) float  g_qkvbuf[(size_t)M_ * NQKV];
__device__ __align__(16) __half g_qh [(size_t)B_*H_*L_*D_];
__device__ __align__(16) __half g_ql [(size_t)B_*H_*L_*D_];
__device__ __align__(16) __half g_kh [(size_t)B_*KV_*L_*D_];
__device__ __align__(16) __half g_vth[(size_t)B_*KV_*D_*L_];

#define CP_ASYNC16(dst, src) \
    asm volatile("cp.async.cg.shared.global [%0], [%1], 16;" :: "r"(dst), "l"(src))
#define CP_COMMIT() asm volatile("cp.async.commit_group;")
#define CP_WAIT(n)  asm volatile("cp.async.wait_group %0;" :: "n"(n))

#define LDSM_X4(r0,r1,r2,r3,addr) \
    asm volatile("ldmatrix.sync.aligned.m8n8.x4.shared.b16 {%0,%1,%2,%3}, [%4];" \
        : "=r"(r0),"=r"(r1),"=r"(r2),"=r"(r3) : "r"(addr))
#define MMAF16(c,a0,a1,a2,a3,b0,b1) \
    asm volatile("mma.sync.aligned.m16n8k16.row.col.f32.f16.f16.f32 " \
        "{%0,%1,%2,%3},{%4,%5,%6,%7},{%8,%9},{%0,%1,%2,%3};" \
        : "+f"((c)[0]),"+f"((c)[1]),"+f"((c)[2]),"+f"((c)[3]) \
        : "r"(a0),"r"(a1),"r"(a2),"r"(a3),"r"(b0),"r"(b1))

// ---------------- fp32 -> hi/lo fp16 planes ----------------
__global__ __launch_bounds__(256) void convert_hl(
    const float* __restrict__ src,
    __half* __restrict__ dh, __half* __restrict__ dl, int total)
{
    int i = (blockIdx.x * 256 + threadIdx.x) * 4;
    if (i >= total) return;
    float4 v = *(const float4*)(src + i);
    float f[4] = {v.x, v.y, v.z, v.w};
    __half hi[4], lo[4];
#pragma unroll
    for (int e = 0; e < 4; e++) {
        hi[e] = __float2half_rn(f[e]);
        lo[e] = __float2half_rn(f[e] - __half2float(hi[e]));
    }
    __half2 hp0, hp1, lp0, lp1;
    hp0 = __halves2half2(hi[0], hi[1]); hp1 = __halves2half2(hi[2], hi[3]);
    lp0 = __halves2half2(lo[0], lo[1]); lp1 = __halves2half2(lo[2], lo[3]);
    ((__half2*)(dh + i))[0] = hp0; ((__half2*)(dh + i))[1] = hp1;
    ((__half2*)(dl + i))[0] = lp0; ((__half2*)(dl + i))[1] = lp1;
}

// fp32 -> fp16 hi only (for B-side operands)
__global__ __launch_bounds__(256) void convert_h(
    const float* __restrict__ src, __half* __restrict__ dh, int total)
{
    int i = (blockIdx.x * 256 + threadIdx.x) * 4;
    if (i >= total) return;
    float4 v = *(const float4*)(src + i);
    ((__half2*)(dh + i))[0] = __floats2half2_rn(v.x, v.y);
    ((__half2*)(dh + i))[1] = __floats2half2_rn(v.z, v.w);
}

// ---------------- 2-term split-fp16 GEMM: C = (Ah+Al) * Bh^T ----------------
// 128x128 tile, BK=32, 3-stage cp.async, 256 threads (2m x 4n warps, 64x32 warp tile).
#define MAT_B 10240                   // one 128x40-elem tile, bytes
#define ST_B  (3 * MAT_B)             // Ah|Al|Bh per stage = 30720
#define GSMF  (3 * ST_B)              // 92160

__global__ __launch_bounds__(256, 2) void gemm_f16(
    const __half* __restrict__ Ah, const __half* __restrict__ Al,
    const __half* __restrict__ Bh,
    float* __restrict__ C, int M, int N, int K)
{
    extern __shared__ __half gsm[];
    const uint32_t smb = (uint32_t)__cvta_generic_to_shared(gsm);

    const int tid  = threadIdx.x;
    const int m0   = blockIdx.y * 128;
    const int n0   = blockIdx.x * 128;
    const int wid  = tid >> 5;
    const int lane = tid & 31;
    const int wm   = wid & 1;          // m half (64)
    const int wn   = wid >> 1;         // n quarter (32)

    float acc[4][4][4];
#pragma unroll
    for (int i = 0; i < 4; i++)
#pragma unroll
        for (int j = 0; j < 4; j++)
#pragma unroll
            for (int r = 0; r < 4; r++) acc[i][j][r] = 0.f;

    auto load_stage = [&](int st, int kt) {
        const int k0 = kt * 32;
        const uint32_t base = smb + st * ST_B;
#pragma unroll
        for (int it = 0; it < 2; it++) {
            int t = tid + it * 256;          // 512 chunks per matrix
            int r = t >> 2, c = t & 3;
            uint32_t so = (uint32_t)(r * 80 + c * 16);
            size_t goA = (size_t)(m0 + r) * K + k0 + c * 8;
            size_t goB = (size_t)(n0 + r) * K + k0 + c * 8;
            CP_ASYNC16(base + so,             Ah + goA);
            CP_ASYNC16(base + MAT_B + so,     Al + goA);
            CP_ASYNC16(base + 2 * MAT_B + so, Bh + goB);
        }
    };

    const int KT = K / 32;
    load_stage(0, 0); CP_COMMIT();
    load_stage(1, 1); CP_COMMIT();

    int slot = 0;
    for (int kt = 0; kt < KT; kt++) {
        CP_WAIT(1);
        __syncthreads();
        if (kt + 2 < KT) {
            int s2 = slot + 2; if (s2 >= 3) s2 -= 3;
            load_stage(s2, kt + 2);
        }
        CP_COMMIT();

        const uint32_t sb  = smb + slot * ST_B;
        const uint32_t sbl = sb + MAT_B;
        const uint32_t bbh = sb + 2 * MAT_B;

#pragma unroll
        for (int ks = 0; ks < 2; ks++) {
            uint32_t ah[4][4], al4[4][4];
#pragma unroll
            for (int mi = 0; mi < 4; mi++) {
                int row = wm * 64 + mi * 16 + (lane & 15);
                uint32_t off = row * 80 + ks * 32 + ((lane >> 4) << 4);
                LDSM_X4(ah[mi][0], ah[mi][1], ah[mi][2], ah[mi][3], sb + off);
                LDSM_X4(al4[mi][0], al4[mi][1], al4[mi][2], al4[mi][3], sbl + off);
            }
            uint32_t bh4[2][4];
#pragma unroll
            for (int ng = 0; ng < 2; ng++) {
                int row = wn * 32 + ng * 16 + (lane & 15);
                uint32_t off = row * 80 + ks * 32 + ((lane >> 4) << 4);
                LDSM_X4(bh4[ng][0], bh4[ng][1], bh4[ng][2], bh4[ng][3], bbh + off);
            }
#pragma unroll
            for (int mi = 0; mi < 4; mi++)
#pragma unroll
                for (int ng = 0; ng < 2; ng++) {
                    float* c0 = acc[mi][2 * ng];
                    float* c1 = acc[mi][2 * ng + 1];
                    MMAF16(c0, ah[mi][0], ah[mi][1], ah[mi][2], ah[mi][3],
                           bh4[ng][0], bh4[ng][2]);
                    MMAF16(c0, al4[mi][0], al4[mi][1], al4[mi][2], al4[mi][3],
                           bh4[ng][0], bh4[ng][2]);
                    MMAF16(c1, ah[mi][0], ah[mi][1], ah[mi][2], ah[mi][3],
                           bh4[ng][1], bh4[ng][3]);
                    MMAF16(c1, al4[mi][0], al4[mi][1], al4[mi][2], al4[mi][3],
                           bh4[ng][1], bh4[ng][3]);
                }
        }
        if (++slot == 3) slot = 0;
    }

    const int tr = lane >> 2;
    const int tc = (lane & 3) * 2;
#pragma unroll
    for (int mi = 0; mi < 4; mi++)
#pragma unroll
        for (int ni = 0; ni < 4; ni++) {
            int row = m0 + wm * 64 + mi * 16 + tr;
            int col = n0 + wn * 32 + ni * 8 + tc;
            *(float2*)(C + (size_t)row * N + col) =
                make_float2(acc[mi][ni][0], acc[mi][ni][1]);
            *(float2*)(C + (size_t)(row + 8) * N + col) =
                make_float2(acc[mi][ni][2], acc[mi][ni][3]);
        }
}

// ---------------- QK RMSNorm + RoPE + split outputs (+ V transpose) ----------------
__global__ __launch_bounds__(128) void norm_rope_split(
    const float* __restrict__ qkv,
    const float* __restrict__ cosT, const float* __restrict__ sinT,
    const float* __restrict__ qw,   const float* __restrict__ kw,
    __half* __restrict__ qh, __half* __restrict__ ql,
    __half* __restrict__ kh, __half* __restrict__ vth)
{
    const int l  = blockIdx.x;
    const int b  = blockIdx.y;
    const int hh = blockIdx.z;
    const int d  = threadIdx.x;
    const size_t m = (size_t)b * L_ + l;

    if (hh >= H_ + KV_) {                 // V path: hi only, transposed
        const int kv = hh - (H_ + KV_);
        float x = qkv[m * NQKV + HID + KV_ * D_ + kv * D_ + d];
        size_t idx = ((size_t)(b * KV_ + kv) * D_ + d) * L_ + l;
        vth[idx] = __float2half_rn(x);
        return;
    }

    float x;
    if (hh < H_) x = qkv[m * NQKV + hh * D_ + d];
    else         x = qkv[m * NQKV + HID + (hh - H_) * D_ + d];

    __shared__ float red[4];
    __shared__ float xn[128];

    float v = x * x;
#pragma unroll
    for (int o = 16; o > 0; o >>= 1) v += __shfl_xor_sync(0xffffffffu, v, o);
    if ((d & 31) == 0) red[d >> 5] = v;
    __syncthreads();
    float total = red[0] + red[1] + red[2] + red[3];
    float rms = rsqrtf(total * (1.0f / 128.0f) + 1e-6f);
    float w = (hh < H_) ? qw[d] : kw[d];
    float xv = x * rms * w;
    xn[d] = xv;
    __syncthreads();

    float c = cosT[l * D_ + d];
    float s = sinT[l * D_ + d];
    float rot = (d < 64) ? -xn[d + 64] : xn[d - 64];
    float out = xv * c + rot * s;

    if (hh < H_) {                        // Q: hi + lo
        size_t idx = (((size_t)(b * H_ + hh)) * L_ + l) * D_ + d;
        __half hi = __float2half_rn(out);
        qh[idx] = hi;
        ql[idx] = __float2half_rn(out - __half2float(hi));
    } else {                              // K: hi only
        size_t idx = (((size_t)(b * KV_ + (hh - H_))) * L_ + l) * D_ + d;
        kh[idx] = __float2half_rn(out);
    }
}

// ---------------- fp16 tensor-core banded flash attention, double-buffered KV ----------------
// smem (elems): Qh 0 | Ql 17408 | stage s at 34816 + s*17920: Kh +0 (8704) | Vth +8704 (9216)
#define AQH 0
#define AQL 17408
#define AKV0 34816
#define AKVSTR 17920
#define ATTN_SMEM_ELEMS (AKV0 + 2 * AKVSTR)
#define ATTN_SMEM_BYTES (ATTN_SMEM_ELEMS * 2)   // 141312

__device__ __forceinline__ uint32_t pkhi(float x, float y) {
    __half2 t = __floats2half2_rn(x, y);
    return *reinterpret_cast<uint32_t*>(&t);
}
__device__ __forceinline__ uint32_t pklo(float x, float y) {
    __half hx = __float2half_rn(x), hy = __float2half_rn(y);
    __half2 t = __floats2half2_rn(x - __half2float(hx), y - __half2float(hy));
    return *reinterpret_cast<uint32_t*>(&t);
}

__global__ __launch_bounds__(256) void attn_mma_kernel(
    const __half* __restrict__ qhg, const __half* __restrict__ qlg,
    const __half* __restrict__ khg, const __half* __restrict__ vhg,
    __half* __restrict__ aoh, __half* __restrict__ aol)
{
    extern __shared__ __half sm[];

    const int tid  = threadIdx.x;
    const int wid  = tid >> 5;
    const int lane = tid & 31;
    const int qb   = blockIdx.x;
    const int bh   = blockIdx.y;
    const int b    = bh >> 4;
    const int h    = bh & 15;
    const int kv   = h >> 2;
    const int q0   = qb * 128;
    const float scale = 0.08838834764831845f;

    const uint32_t smb  = (uint32_t)__cvta_generic_to_shared(sm);
    const uint32_t qh_b = smb + AQH * 2;
    const uint32_t ql_b = smb + AQL * 2;

    const __half* kh_src = khg + ((size_t)(b * KV_ + kv)) * L_ * D_;
    const __half* vh_src = vhg + ((size_t)(b * KV_ + kv) * D_) * L_;

    auto load_kv = [&](int st, int tk) {
        const int j0 = tk * 64;
        const uint32_t khb = smb + (AKV0 + st * AKVSTR) * 2;
        const uint32_t vhb = khb + 8704 * 2;
#pragma unroll
        for (int t = tid; t < 64 * 16; t += 256) {
            int r = t >> 4, c = (t & 15) * 8;
            CP_ASYNC16(khb + (r * 136 + c) * 2, kh_src + (size_t)(j0 + r) * D_ + c);
        }
#pragma unroll
        for (int t = tid; t < 128 * 8; t += 256) {
            int d = t >> 3, c = (t & 7) * 8;
            CP_ASYNC16(vhb + (d * 72 + c) * 2, vh_src + (size_t)d * L_ + j0 + c);
        }
    };

    {
        const __half* ph = qhg + (((size_t)(b * H_ + h)) * L_ + q0) * D_;
        const __half* pl = qlg + (((size_t)(b * H_ + h)) * L_ + q0) * D_;
        for (int t = tid; t < 128 * 16; t += 256) {
            int r = t >> 4, c = (t & 15) * 8;
            *(uint4*)(sm + AQH + r * 136 + c) = *(const uint4*)(ph + r * 128 + c);
            *(uint4*)(sm + AQL + r * 136 + c) = *(const uint4*)(pl + r * 128 + c);
        }
    }

    float o[16][4];
#pragma unroll
    for (int n = 0; n < 16; n++)
#pragma unroll
        for (int e = 0; e < 4; e++) o[n][e] = 0.f;
    float mrow[2] = {-1e30f, -1e30f};
    float lrow[2] = {0.f, 0.f};

    const int i1 = q0 + wid * 16 + (lane >> 2);
    const int i2 = i1 + 8;

    int t_lo = (q0 - WIN_) >> 6; if (t_lo < 0) t_lo = 0;
    int t_hi = (q0 + 127 + WIN_) >> 6; if (t_hi > L_ / 64 - 1) t_hi = L_ / 64 - 1;

    load_kv(0, t_lo);
    CP_COMMIT();

    for (int tk = t_lo; tk <= t_hi; tk++) {
        const int st = (tk - t_lo) & 1;
        const int j0 = tk * 64;

        CP_WAIT(0);
        __syncthreads();
        if (tk < t_hi) { load_kv(st ^ 1, tk + 1); }
        CP_COMMIT();

        const uint32_t kh_b = smb + (AKV0 + st * AKVSTR) * 2;
        const uint32_t vh_b = kh_b + 8704 * 2;

        // ---- S = Qh*Kh + Ql*Kh ----
        float s[8][4];
#pragma unroll
        for (int n = 0; n < 8; n++)
#pragma unroll
            for (int e = 0; e < 4; e++) s[n][e] = 0.f;

#pragma unroll
        for (int pass = 0; pass < 2; pass++) {
            const uint32_t ab = (pass == 1) ? ql_b : qh_b;
#pragma unroll
            for (int k8 = 0; k8 < 8; k8++) {
                uint32_t a0, a1, a2, a3;
                uint32_t aaddr = ab + ((wid * 16 + (lane & 15)) * 136
                                       + k8 * 16 + ((lane >> 4) * 8)) * 2;
                LDSM_X4(a0, a1, a2, a3, aaddr);
#pragma unroll
                for (int n2 = 0; n2 < 4; n2++) {
                    uint32_t b0, b1, b2, b3;
                    uint32_t baddr = kh_b + ((n2 * 16 + (lane & 15)) * 136
                                             + k8 * 16 + ((lane >> 4) * 8)) * 2;
                    LDSM_X4(b0, b1, b2, b3, baddr);
                    MMAF16(s[2 * n2],     a0, a1, a2, a3, b0, b2);
                    MMAF16(s[2 * n2 + 1], a0, a1, a2, a3, b1, b3);
                }
            }
        }

        // ---- mask + scale ----
#pragma unroll
        for (int n = 0; n < 8; n++) {
            const int jc = j0 + n * 8 + (lane & 3) * 2;
#pragma unroll
            for (int e = 0; e < 4; e++) {
                const int i = (e < 2) ? i1 : i2;
                const int j = jc + (e & 1);
                const bool valid = (unsigned)(i - j + WIN_) <= (unsigned)(2 * WIN_);
                s[n][e] = valid ? s[n][e] * scale : -1e30f;
            }
        }

        // ---- online softmax ----
        float m1 = -1e30f, m2 = -1e30f;
#pragma unroll
        for (int n = 0; n < 8; n++) {
            m1 = fmaxf(m1, fmaxf(s[n][0], s[n][1]));
            m2 = fmaxf(m2, fmaxf(s[n][2], s[n][3]));
        }
        m1 = fmaxf(m1, __shfl_xor_sync(0xffffffffu, m1, 1));
        m1 = fmaxf(m1, __shfl_xor_sync(0xffffffffu, m1, 2));
        m2 = fmaxf(m2, __shfl_xor_sync(0xffffffffu, m2, 1));
        m2 = fmaxf(m2, __shfl_xor_sync(0xffffffffu, m2, 2));
        const float mn1 = fmaxf(mrow[0], m1);
        const float mn2 = fmaxf(mrow[1], m2);
        const float al1 = __expf(mrow[0] - mn1);
        const float al2 = __expf(mrow[1] - mn2);
        float ls1 = 0.f, ls2 = 0.f;
#pragma unroll
        for (int n = 0; n < 8; n++) {
            s[n][0] = __expf(s[n][0] - mn1);
            s[n][1] = __expf(s[n][1] - mn1);
            s[n][2] = __expf(s[n][2] - mn2);
            s[n][3] = __expf(s[n][3] - mn2);
            ls1 += s[n][0] + s[n][1];
            ls2 += s[n][2] + s[n][3];
        }
        ls1 += __shfl_xor_sync(0xffffffffu, ls1, 1);
        ls1 += __shfl_xor_sync(0xffffffffu, ls1, 2);
        ls2 += __shfl_xor_sync(0xffffffffu, ls2, 1);
        ls2 += __shfl_xor_sync(0xffffffffu, ls2, 2);
        lrow[0] = al1 * lrow[0] + ls1;
        lrow[1] = al2 * lrow[1] + ls2;
        mrow[0] = mn1;
        mrow[1] = mn2;
#pragma unroll
        for (int n = 0; n < 16; n++) {
            o[n][0] *= al1; o[n][1] *= al1;
            o[n][2] *= al2; o[n][3] *= al2;
        }

        // ---- O += Ph*Vh + Pl*Vh ----
#pragma unroll
        for (int kk = 0; kk < 4; kk++) {
            const int t0 = 2 * kk, t1 = 2 * kk + 1;
            uint32_t ah[4], al[4];
            ah[0] = pkhi(s[t0][0], s[t0][1]); ah[1] = pkhi(s[t0][2], s[t0][3]);
            ah[2] = pkhi(s[t1][0], s[t1][1]); ah[3] = pkhi(s[t1][2], s[t1][3]);
            al[0] = pklo(s[t0][0], s[t0][1]); al[1] = pklo(s[t0][2], s[t0][3]);
            al[2] = pklo(s[t1][0], s[t1][1]); al[3] = pklo(s[t1][2], s[t1][3]);
#pragma unroll
            for (int n2 = 0; n2 < 8; n2++) {
                uint32_t h0, h1, h2, h3;
                uint32_t va = ((n2 * 16 + (lane & 15)) * 72
                               + kk * 16 + ((lane >> 4) * 8)) * 2;
                LDSM_X4(h0, h1, h2, h3, vh_b + va);
                MMAF16(o[2 * n2],     ah[0], ah[1], ah[2], ah[3], h0, h2);
                MMAF16(o[2 * n2],     al[0], al[1], al[2], al[3], h0, h2);
                MMAF16(o[2 * n2 + 1], ah[0], ah[1], ah[2], ah[3], h1, h3);
                MMAF16(o[2 * n2 + 1], al[0], al[1], al[2], al[3], h1, h3);
            }
        }
    }

    // ---- epilogue: /l, write hi/lo fp16 planes ----
    const float inv1 = 1.0f / lrow[0];
    const float inv2 = 1.0f / lrow[1];
    const size_t m1r = (size_t)b * L_ + i1;
    const size_t m2r = (size_t)b * L_ + i2;
#pragma unroll
    for (int n = 0; n < 16; n++) {
        const int col = h * 128 + n * 8 + (lane & 3) * 2;
        {
            float v0 = o[n][0] * inv1, v1 = o[n][1] * inv1;
            __half h0 = __float2half_rn(v0), h1v = __float2half_rn(v1);
            *(__half2*)(aoh + m1r * KK + col) = __halves2half2(h0, h1v);
            *(__half2*)(aol + m1r * KK + col) =
                __floats2half2_rn(v0 - __half2float(h0), v1 - __half2float(h1v));
        }
        {
            float v0 = o[n][2] * inv2, v1 = o[n][3] * inv2;
            __half h0 = __float2half_rn(v0), h1v = __float2half_rn(v1);
            *(__half2*)(aoh + m2r * KK + col) = __halves2half2(h0, h1v);
            *(__half2*)(aol + m2r * KK + col) =
                __floats2half2_rn(v0 - __half2float(h0), v1 - __half2float(h1v));
        }
    }
}

// ---------------- launch ----------------
extern "C" void kernel_launch(void* const* d_in, const int* in_sizes, int n_in,
                              void* d_out, int out_size)
{
    const float* x    = (const float*)d_in[0];
    const float* cosT = (const float*)d_in[1];
    const float* sinT = (const float*)d_in[2];
    const float* Wq   = (const float*)d_in[3];
    const float* Wk   = (const float*)d_in[4];
    const float* Wv   = (const float*)d_in[5];
    const float* Wo   = (const float*)d_in[6];
    const float* qw   = (const float*)d_in[7];
    const float* kw   = (const float*)d_in[8];
    float* out = (float*)d_out;

    __half *xh, *xl, *wqkvh, *woh, *aoh, *aol, *qh, *ql, *kh, *vth;
    float *qkvbuf;
    cudaGetSymbolAddress((void**)&xh,     g_xh);
    cudaGetSymbolAddress((void**)&xl,     g_xl);
    cudaGetSymbolAddress((void**)&wqkvh,  g_wqkvh);
    cudaGetSymbolAddress((void**)&woh,    g_woh);
    cudaGetSymbolAddress((void**)&aoh,    g_aoh);
    cudaGetSymbolAddress((void**)&aol,    g_aol);
    cudaGetSymbolAddress((void**)&qkvbuf, g_qkvbuf);
    cudaGetSymbolAddress((void**)&qh,     g_qh);
    cudaGetSymbolAddress((void**)&ql,     g_ql);
    cudaGetSymbolAddress((void**)&kh,     g_kh);
    cudaGetSymbolAddress((void**)&vth,    g_vth);

    // conversions: x hi+lo; weights hi only
    {
        int tot = M_ * HID;
        convert_hl<<<tot / 1024, 256>>>(x, xh, xl, tot);
        tot = HID * HID;
        convert_h<<<tot / 1024, 256>>>(Wq, wqkvh, tot);
        tot = KV_ * D_ * HID;
        convert_h<<<tot / 1024, 256>>>(Wk, wqkvh + (size_t)HID * KK, tot);
        convert_h<<<tot / 1024, 256>>>(Wv, wqkvh + (size_t)(HID + KV_ * D_) * KK, tot);
        tot = HID * HID;
        convert_h<<<tot / 1024, 256>>>(Wo, woh, tot);
    }

    cudaFuncSetAttribute(gemm_f16,
                         cudaFuncAttributeMaxDynamicSharedMemorySize, GSMF);

    // fused QKV projection
    gemm_f16<<<dim3(NQKV / 128, M_ / 128), 256, GSMF>>>(
        xh, xl, wqkvh, qkvbuf, M_, NQKV, KK);

    // RMSNorm + RoPE + split outputs
    norm_rope_split<<<dim3(L_, B_, H_ + 2 * KV_), 128>>>(
        qkvbuf, cosT, sinT, qw, kw, qh, ql, kh, vth);

    // fp16 tensor-core banded flash attention
    cudaFuncSetAttribute(attn_mma_kernel,
                         cudaFuncAttributeMaxDynamicSharedMemorySize, ATTN_SMEM_BYTES);
    attn_mma_kernel<<<dim3(L_ / 128, B_ * H_), 256, ATTN_SMEM_BYTES>>>(
        qh, ql, kh, vth, aoh, aol);

    // output projection
    gemm_f16<<<dim3(HID / 128, M_ / 128), 256, GSMF>>>(
        aoh, aol, woh, out, M_, HID, KK);
}